// round 2
// baseline (speedup 1.0000x reference)
#include <cuda_runtime.h>
#include <cstdint>

#define N_NODES 50000
#define N_EDGES 800000
#define H 64
#define IN_DIM 121

// Scratch (device globals -- no allocations allowed)
__device__ __align__(16) float g_x0 [N_NODES * H];   // embedding output (sc)
__device__ __align__(16) float g_x  [N_NODES * H];   // current node features
__device__ __align__(16) float g_a  [N_NODES * H];   // x @ W_top  (src half)
__device__ __align__(16) float g_b  [N_NODES * H];   // x @ W_bot  (dst half)
__device__ __align__(16) float g_acc[N_NODES * H];   // scatter accumulator

__device__ __forceinline__ float silu_f(float z) {
    return z * __fdividef(1.0f, 1.0f + __expf(-z));
}

// ---------------------------------------------------------------------------
// Embedding: x = silu(cat[one_hot, pos] @ W + b), W: [121, 64]
// 256 threads = 64 cols x 4 nodes
// ---------------------------------------------------------------------------
__global__ void k_embed(const float* __restrict__ oh, const float* __restrict__ pos,
                        const float* __restrict__ W, const float* __restrict__ bias) {
    __shared__ float in_s[4][IN_DIM];
    const int node0 = blockIdx.x * 4;
    const int tid = threadIdx.x;
    for (int i = tid; i < 4 * IN_DIM; i += 256) {
        int r = i / IN_DIM, k = i % IN_DIM;
        int node = node0 + r;
        float v = 0.0f;
        if (node < N_NODES)
            v = (k < 118) ? oh[(size_t)node * 118 + k] : pos[(size_t)node * 3 + (k - 118)];
        in_s[r][k] = v;
    }
    __syncthreads();
    const int c = tid & 63, r = tid >> 6;
    const int node = node0 + r;
    if (node >= N_NODES) return;
    float acc = bias[c];
    #pragma unroll 11
    for (int k = 0; k < IN_DIM; k++)
        acc = fmaf(in_s[r][k], W[k * 64 + c], acc);
    float v = silu_f(acc);
    g_x0[node * 64 + c] = v;
    g_x [node * 64 + c] = v;
}

// ---------------------------------------------------------------------------
// Per-layer dual GEMM: a = x @ W[0:64], b = x @ W[64:128]; also zeros g_acc.
// 1024 threads = 64 cols x 16 nodes; weights cached in smem.
// ---------------------------------------------------------------------------
__global__ __launch_bounds__(1024) void k_ab(const float* __restrict__ Wl) {
    __shared__ float Ws[2 * 64 * 64];   // 32 KB
    __shared__ float xs[16][64];
    const int tid = threadIdx.x;
    const int node0 = blockIdx.x * 16;
    for (int i = tid; i < 8192; i += 1024) Ws[i] = Wl[i];
    const int c = tid & 63, r = tid >> 6;
    const int node = node0 + r;
    xs[r][c] = g_x[node * 64 + c];
    __syncthreads();
    float a = 0.0f, b = 0.0f;
    #pragma unroll
    for (int k = 0; k < 64; k++) {
        float xv = xs[r][k];
        a = fmaf(xv, Ws[k * 64 + c], a);
        b = fmaf(xv, Ws[4096 + k * 64 + c], b);
    }
    g_a  [node * 64 + c] = a;
    g_b  [node * 64 + c] = b;
    g_acc[node * 64 + c] = 0.0f;
}

// ---------------------------------------------------------------------------
// Edge pass: acc[src] += silu(a[src] + b[dst] + bias)
// 16 threads per edge, float4 lanes, vector red.global.add.v4.f32
// NOTE: edge_index is int32 (JAX x64 disabled downgrades int64 -> int32).
// ---------------------------------------------------------------------------
__global__ void k_edge(const int* __restrict__ ei, const float* __restrict__ bias) {
    const int t = blockIdx.x * blockDim.x + threadIdx.x;
    const int e = t >> 4;
    if (e >= N_EDGES) return;
    const int lane = t & 15;
    const int s = __ldg(ei + e);
    const int d = __ldg(ei + N_EDGES + e);
    const float4 av = *(const float4*)(g_a + (size_t)s * 64 + lane * 4);
    const float4 bv = *(const float4*)(g_b + (size_t)d * 64 + lane * 4);
    const float4 bb = *(const float4*)(bias + lane * 4);
    float4 m;
    m.x = silu_f(av.x + bv.x + bb.x);
    m.y = silu_f(av.y + bv.y + bb.y);
    m.z = silu_f(av.z + bv.z + bb.z);
    m.w = silu_f(av.w + bv.w + bb.w);
    unsigned long long p =
        (unsigned long long)__cvta_generic_to_global(g_acc + (size_t)s * 64 + lane * 4);
    asm volatile("red.global.add.v4.f32 [%0], {%1, %2, %3, %4};"
                 :: "l"(p), "f"(m.x), "f"(m.y), "f"(m.z), "f"(m.w) : "memory");
}

// ---------------------------------------------------------------------------
// Update: x += silu((x + 0.25*acc) @ U + b)
// ---------------------------------------------------------------------------
__global__ __launch_bounds__(1024) void k_update(const float* __restrict__ U,
                                                 const float* __restrict__ bias) {
    __shared__ float Us[64 * 64];       // 16 KB
    __shared__ float hs[16][64];
    const int tid = threadIdx.x;
    const int node0 = blockIdx.x * 16;
    for (int i = tid; i < 4096; i += 1024) Us[i] = U[i];
    const int c = tid & 63, r = tid >> 6;
    const int node = node0 + r;
    hs[r][c] = g_x[node * 64 + c] + 0.25f * g_acc[node * 64 + c];
    __syncthreads();
    float acc = bias[c];
    #pragma unroll
    for (int k = 0; k < 64; k++)
        acc = fmaf(hs[r][k], Us[k * 64 + c], acc);
    g_x[node * 64 + c] += silu_f(acc);
}

// ---------------------------------------------------------------------------
// Output: out = (x0 + x) @ W_out[64,3] + b. One warp per node.
// ---------------------------------------------------------------------------
__global__ void k_out(const float* __restrict__ W, const float* __restrict__ bias,
                      float* __restrict__ out) {
    const int warp = (blockIdx.x * blockDim.x + threadIdx.x) >> 5;
    const int lane = threadIdx.x & 31;
    if (warp >= N_NODES) return;
    const size_t base = (size_t)warp * 64;
    float v0 = g_x0[base + lane]      + g_x[base + lane];
    float v1 = g_x0[base + 32 + lane] + g_x[base + 32 + lane];
    float p0 = fmaf(v0, W[lane * 3 + 0], v1 * W[(lane + 32) * 3 + 0]);
    float p1 = fmaf(v0, W[lane * 3 + 1], v1 * W[(lane + 32) * 3 + 1]);
    float p2 = fmaf(v0, W[lane * 3 + 2], v1 * W[(lane + 32) * 3 + 2]);
    #pragma unroll
    for (int off = 16; off > 0; off >>= 1) {
        p0 += __shfl_down_sync(0xFFFFFFFFu, p0, off);
        p1 += __shfl_down_sync(0xFFFFFFFFu, p1, off);
        p2 += __shfl_down_sync(0xFFFFFFFFu, p2, off);
    }
    if (lane == 0) {
        out[warp * 3 + 0] = p0 + bias[0];
        out[warp * 3 + 1] = p1 + bias[1];
        out[warp * 3 + 2] = p2 + bias[2];
    }
}

extern "C" void kernel_launch(void* const* d_in, const int* in_sizes, int n_in,
                              void* d_out, int out_size) {
    const float* oh   = (const float*)d_in[0];
    const float* pos  = (const float*)d_in[1];
    const int*   ei   = (const int*)d_in[2];     // int32 edge_index [2, E]
    const float* embW = (const float*)d_in[3];
    const float* embB = (const float*)d_in[4];
    const float* iW   = (const float*)d_in[5];   // [4, 128, 64]
    const float* iB   = (const float*)d_in[6];   // [4, 64]
    const float* uW   = (const float*)d_in[7];   // [4, 64, 64]
    const float* uB   = (const float*)d_in[8];   // [4, 64]
    const float* oW   = (const float*)d_in[9];   // [64, 3]
    const float* oB   = (const float*)d_in[10];  // [3]
    float* out = (float*)d_out;

    k_embed<<<(N_NODES + 3) / 4, 256>>>(oh, pos, embW, embB);
    for (int l = 0; l < 4; l++) {
        k_ab<<<N_NODES / 16, 1024>>>(iW + (size_t)l * 2 * 64 * 64);
        k_edge<<<(N_EDGES * 16 + 255) / 256, 256>>>(ei, iB + l * 64);
        k_update<<<N_NODES / 16, 1024>>>(uW + (size_t)l * 64 * 64, uB + l * 64);
    }
    k_out<<<(N_NODES * 32 + 255) / 256, 256>>>(oW, oB, out);
}

// round 3
// speedup vs baseline: 1.2516x; 1.2516x over previous
#include <cuda_runtime.h>
#include <cstdint>

#define N_NODES 50000
#define N_EDGES 800000
#define H 64

// ---------------- scratch (device globals; no allocations) ----------------
__device__ __align__(16) float g_x0 [N_NODES * H];
__device__ __align__(16) float g_x  [N_NODES * H];
__device__ __align__(16) float g_a  [N_NODES * H];
__device__ __align__(16) float g_b  [N_NODES * H];
__device__ __align__(16) float g_acc[N_NODES * H];
__device__ int g_deg[N_NODES];
__device__ int g_off[N_NODES + 1];
__device__ int g_cursor[N_NODES];
__device__ int g_csr[N_EDGES];

__device__ __forceinline__ float silu_f(float z) {
    return z * __fdividef(1.0f, 1.0f + __expf(-z));
}
__device__ __forceinline__ float4 silu4(float4 z) {
    return make_float4(silu_f(z.x), silu_f(z.y), silu_f(z.z), silu_f(z.w));
}

// ============================ CSR construction =============================
__global__ void k_zero_deg() {
    int i = blockIdx.x * blockDim.x + threadIdx.x;
    if (i < N_NODES) g_deg[i] = 0;
}

__global__ void k_hist(const int* __restrict__ ei) {
    int e = blockIdx.x * blockDim.x + threadIdx.x;
    if (e < N_EDGES) atomicAdd(&g_deg[ei[e]], 1);
}

// single-block shfl-based scan over 50000 ints
__global__ __launch_bounds__(1024) void k_scan() {
    __shared__ int warp_sums[32];
    __shared__ int s_carry;
    const int tid = threadIdx.x, lane = tid & 31, w = tid >> 5;
    if (tid == 0) { g_off[0] = 0; s_carry = 0; }
    __syncthreads();
    for (int base = 0; base < N_NODES; base += 1024) {
        int i = base + tid;
        int v = (i < N_NODES) ? g_deg[i] : 0;
        int x = v;
        #pragma unroll
        for (int o = 1; o < 32; o <<= 1) {
            int t = __shfl_up_sync(0xFFFFFFFFu, x, o);
            if (lane >= o) x += t;
        }
        if (lane == 31) warp_sums[w] = x;
        __syncthreads();
        if (w == 0) {
            int ws = warp_sums[lane];
            #pragma unroll
            for (int o = 1; o < 32; o <<= 1) {
                int t = __shfl_up_sync(0xFFFFFFFFu, ws, o);
                if (lane >= o) ws += t;
            }
            warp_sums[lane] = ws;
        }
        __syncthreads();
        int incl = x + (w ? warp_sums[w - 1] : 0) + s_carry;
        if (i < N_NODES) { g_off[i + 1] = incl; g_cursor[i] = incl - v; }
        __syncthreads();
        if (tid == 1023) s_carry = incl;
        __syncthreads();
    }
}

__global__ void k_scatter(const int* __restrict__ ei) {
    int e = blockIdx.x * blockDim.x + threadIdx.x;
    if (e < N_EDGES) {
        int s = ei[e];
        int p = atomicAdd(&g_cursor[s], 1);
        g_csr[p] = ei[N_EDGES + e];
    }
}

// ====================== fused embed + interact-GEMM(0) =====================
// 40 nodes/block, 640 threads; thread = 1 row x 4 cols.
// dyn smem: embW[121*64] | Wab[8192] | in_s[40*121] | xs[40*64]
__global__ __launch_bounds__(640) void k_embed_ab(
    const float* __restrict__ oh, const float* __restrict__ pos,
    const float* __restrict__ embW, const float* __restrict__ embB,
    const float* __restrict__ Wab0) {
    extern __shared__ float smem[];
    float* Ws   = smem;               // 7744
    float* Wab  = smem + 7744;        // 8192
    float* in_s = smem + 7744 + 8192; // 4840
    float* xs   = in_s + 4840;        // 2560
    const int tid = threadIdx.x;
    const int node0 = blockIdx.x * 40;
    // weight loads
    {
        float4* d = (float4*)Ws; const float4* s = (const float4*)embW;
        for (int i = tid; i < 7744 / 4; i += 640) d[i] = s[i];
        float4* d2 = (float4*)Wab; const float4* s2 = (const float4*)Wab0;
        for (int i = tid; i < 8192 / 4; i += 640) d2[i] = s2[i];
    }
    // input staging
    for (int i = tid; i < 40 * 118; i += 640) {
        int row = i / 118, k = i % 118;
        in_s[row * 121 + k] = oh[(size_t)(node0 + row) * 118 + k];
    }
    for (int i = tid; i < 40 * 3; i += 640) {
        int row = i / 3, k = i % 3;
        in_s[row * 121 + 118 + k] = pos[(size_t)(node0 + row) * 3 + k];
    }
    __syncthreads();
    const int r = tid >> 4, cg = tid & 15;
    const int node = node0 + r;
    const float4* Ws4 = (const float4*)Ws;
    // phase 1: embedding GEMM
    float4 acc = __ldg((const float4*)(embB) + cg);
    #pragma unroll 8
    for (int k = 0; k < 121; k++) {
        float h = in_s[r * 121 + k];
        float4 w = Ws4[k * 16 + cg];
        acc.x = fmaf(h, w.x, acc.x); acc.y = fmaf(h, w.y, acc.y);
        acc.z = fmaf(h, w.z, acc.z); acc.w = fmaf(h, w.w, acc.w);
    }
    float4 xv = silu4(acc);
    *(float4*)(g_x0 + (size_t)node * 64 + cg * 4) = xv;
    *(float4*)(g_x  + (size_t)node * 64 + cg * 4) = xv;
    ((float4*)xs)[r * 16 + cg] = xv;
    __syncthreads();
    // phase 2: a = x @ Wa, b = x @ Wb
    const float4* Wa4 = (const float4*)Wab;
    const float4* Wb4 = Wa4 + 1024;
    float4 a4 = make_float4(0, 0, 0, 0), b4 = a4;
    #pragma unroll 8
    for (int k = 0; k < 64; k++) {
        float x = xs[r * 64 + k];
        float4 wa = Wa4[k * 16 + cg], wb = Wb4[k * 16 + cg];
        a4.x = fmaf(x, wa.x, a4.x); a4.y = fmaf(x, wa.y, a4.y);
        a4.z = fmaf(x, wa.z, a4.z); a4.w = fmaf(x, wa.w, a4.w);
        b4.x = fmaf(x, wb.x, b4.x); b4.y = fmaf(x, wb.y, b4.y);
        b4.z = fmaf(x, wb.z, b4.z); b4.w = fmaf(x, wb.w, b4.w);
    }
    *(float4*)(g_a + (size_t)node * 64 + cg * 4) = a4;
    *(float4*)(g_b + (size_t)node * 64 + cg * 4) = b4;
}

// ========================== CSR edge aggregation ===========================
// acc[s][c] = sum_{d in N(s)} silu(a[s][c] + b[d][c] + bias[c])
// 8 nodes/block, 64 threads/node.
__global__ __launch_bounds__(512) void k_edge(const float* __restrict__ bias) {
    const int tid = threadIdx.x;
    const int s = blockIdx.x * 8 + (tid >> 6);
    const int c = tid & 63;
    const float asb = g_a[(size_t)s * 64 + c] + __ldg(bias + c);
    int j = g_off[s];
    const int end = g_off[s + 1];
    float acc = 0.0f;
    if (j < end) {
        int d = __ldg(g_csr + j);
        float bv = g_b[(size_t)d * 64 + c];
        for (++j; j < end; ++j) {
            int dn = __ldg(g_csr + j);
            float bn = g_b[(size_t)dn * 64 + c];
            acc += silu_f(asb + bv);
            bv = bn;
        }
        acc += silu_f(asb + bv);
    }
    g_acc[(size_t)s * 64 + c] = acc;
}

// =================== fused update(l) + interact-GEMM(l+1) ==================
// dyn smem: U[4096] | Wab[8192] | xs[2560] | hs[2560]
__global__ __launch_bounds__(640) void k_update_ab(
    const float* __restrict__ U, const float* __restrict__ ub,
    const float* __restrict__ Wabn) {
    extern __shared__ float smem[];
    float* Us  = smem;
    float* Wab = smem + 4096;
    float* xs  = smem + 4096 + 8192;
    float* hs  = xs + 2560;
    const int tid = threadIdx.x;
    const int node0 = blockIdx.x * 40;
    {
        float4* d = (float4*)Us; const float4* s = (const float4*)U;
        for (int i = tid; i < 1024; i += 640) d[i] = s[i];
        float4* d2 = (float4*)Wab; const float4* s2 = (const float4*)Wabn;
        for (int i = tid; i < 2048; i += 640) d2[i] = s2[i];
    }
    {
        int row = tid >> 4, c4 = tid & 15;
        float4 xv = *(const float4*)(g_x   + (size_t)(node0 + row) * 64 + c4 * 4);
        float4 av = *(const float4*)(g_acc + (size_t)(node0 + row) * 64 + c4 * 4);
        ((float4*)xs)[tid] = xv;
        ((float4*)hs)[tid] = make_float4(xv.x + 0.25f * av.x, xv.y + 0.25f * av.y,
                                         xv.z + 0.25f * av.z, xv.w + 0.25f * av.w);
    }
    __syncthreads();
    const int r = tid >> 4, cg = tid & 15;
    const int node = node0 + r;
    const float4* Us4 = (const float4*)Us;
    float4 acc = __ldg((const float4*)(ub) + cg);
    #pragma unroll 8
    for (int k = 0; k < 64; k++) {
        float h = hs[r * 64 + k];
        float4 w = Us4[k * 16 + cg];
        acc.x = fmaf(h, w.x, acc.x); acc.y = fmaf(h, w.y, acc.y);
        acc.z = fmaf(h, w.z, acc.z); acc.w = fmaf(h, w.w, acc.w);
    }
    float4 sv = silu4(acc);
    float4 xo = ((float4*)xs)[r * 16 + cg];
    float4 xn = make_float4(xo.x + sv.x, xo.y + sv.y, xo.z + sv.z, xo.w + sv.w);
    *(float4*)(g_x + (size_t)node * 64 + cg * 4) = xn;
    ((float4*)xs)[r * 16 + cg] = xn;
    __syncthreads();
    const float4* Wa4 = (const float4*)Wab;
    const float4* Wb4 = Wa4 + 1024;
    float4 a4 = make_float4(0, 0, 0, 0), b4 = a4;
    #pragma unroll 8
    for (int k = 0; k < 64; k++) {
        float x = xs[r * 64 + k];
        float4 wa = Wa4[k * 16 + cg], wb = Wb4[k * 16 + cg];
        a4.x = fmaf(x, wa.x, a4.x); a4.y = fmaf(x, wa.y, a4.y);
        a4.z = fmaf(x, wa.z, a4.z); a4.w = fmaf(x, wa.w, a4.w);
        b4.x = fmaf(x, wb.x, b4.x); b4.y = fmaf(x, wb.y, b4.y);
        b4.z = fmaf(x, wb.z, b4.z); b4.w = fmaf(x, wb.w, b4.w);
    }
    *(float4*)(g_a + (size_t)node * 64 + cg * 4) = a4;
    *(float4*)(g_b + (size_t)node * 64 + cg * 4) = b4;
}

// ====================== fused update(3) + output head ======================
__global__ __launch_bounds__(640) void k_update_out(
    const float* __restrict__ U, const float* __restrict__ ub,
    const float* __restrict__ Wo, const float* __restrict__ bo,
    float* __restrict__ out) {
    __shared__ float Us[4096];
    __shared__ float xs[2560];
    __shared__ float hs[2560];
    __shared__ float Wos[192];
    const int tid = threadIdx.x;
    const int node0 = blockIdx.x * 40;
    {
        float4* d = (float4*)Us; const float4* s = (const float4*)U;
        for (int i = tid; i < 1024; i += 640) d[i] = s[i];
        if (tid < 192) Wos[tid] = Wo[tid];
    }
    {
        int row = tid >> 4, c4 = tid & 15;
        float4 xv = *(const float4*)(g_x   + (size_t)(node0 + row) * 64 + c4 * 4);
        float4 av = *(const float4*)(g_acc + (size_t)(node0 + row) * 64 + c4 * 4);
        ((float4*)xs)[tid] = xv;
        ((float4*)hs)[tid] = make_float4(xv.x + 0.25f * av.x, xv.y + 0.25f * av.y,
                                         xv.z + 0.25f * av.z, xv.w + 0.25f * av.w);
    }
    __syncthreads();
    const int r = tid >> 4, cg = tid & 15;
    const int node = node0 + r;
    const float4* Us4 = (const float4*)Us;
    float4 acc = __ldg((const float4*)(ub) + cg);
    #pragma unroll 8
    for (int k = 0; k < 64; k++) {
        float h = hs[r * 64 + k];
        float4 w = Us4[k * 16 + cg];
        acc.x = fmaf(h, w.x, acc.x); acc.y = fmaf(h, w.y, acc.y);
        acc.z = fmaf(h, w.z, acc.z); acc.w = fmaf(h, w.w, acc.w);
    }
    float4 sv = silu4(acc);
    float4 xo = ((float4*)xs)[r * 16 + cg];
    float4 x0v = *(const float4*)(g_x0 + (size_t)node * 64 + cg * 4);
    // v = x0 + x_old + silu(...)
    float4 v = make_float4(x0v.x + xo.x + sv.x, x0v.y + xo.y + sv.y,
                           x0v.z + xo.z + sv.z, x0v.w + xo.w + sv.w);
    float p0 = 0, p1 = 0, p2 = 0;
    const int cb = cg * 4;
    p0 = v.x * Wos[(cb + 0) * 3 + 0] + v.y * Wos[(cb + 1) * 3 + 0]
       + v.z * Wos[(cb + 2) * 3 + 0] + v.w * Wos[(cb + 3) * 3 + 0];
    p1 = v.x * Wos[(cb + 0) * 3 + 1] + v.y * Wos[(cb + 1) * 3 + 1]
       + v.z * Wos[(cb + 2) * 3 + 1] + v.w * Wos[(cb + 3) * 3 + 1];
    p2 = v.x * Wos[(cb + 0) * 3 + 2] + v.y * Wos[(cb + 1) * 3 + 2]
       + v.z * Wos[(cb + 2) * 3 + 2] + v.w * Wos[(cb + 3) * 3 + 2];
    #pragma unroll
    for (int off = 8; off > 0; off >>= 1) {
        p0 += __shfl_down_sync(0xFFFFFFFFu, p0, off, 16);
        p1 += __shfl_down_sync(0xFFFFFFFFu, p1, off, 16);
        p2 += __shfl_down_sync(0xFFFFFFFFu, p2, off, 16);
    }
    if (cg == 0) {
        out[node * 3 + 0] = p0 + __ldg(bo + 0);
        out[node * 3 + 1] = p1 + __ldg(bo + 1);
        out[node * 3 + 2] = p2 + __ldg(bo + 2);
    }
}

// ================================ launcher =================================
extern "C" void kernel_launch(void* const* d_in, const int* in_sizes, int n_in,
                              void* d_out, int out_size) {
    const float* oh   = (const float*)d_in[0];
    const float* pos  = (const float*)d_in[1];
    const int*   ei   = (const int*)d_in[2];
    const float* embW = (const float*)d_in[3];
    const float* embB = (const float*)d_in[4];
    const float* iW   = (const float*)d_in[5];   // [4, 128, 64]
    const float* iB   = (const float*)d_in[6];   // [4, 64]
    const float* uW   = (const float*)d_in[7];   // [4, 64, 64]
    const float* uB   = (const float*)d_in[8];   // [4, 64]
    const float* oW   = (const float*)d_in[9];   // [64, 3]
    const float* oB   = (const float*)d_in[10];  // [3]
    float* out = (float*)d_out;

    const int EMBED_SMEM  = (7744 + 8192 + 4840 + 2560) * 4;  // 93,344 B
    const int UPDATE_SMEM = (4096 + 8192 + 2560 + 2560) * 4;  // 69,632 B
    cudaFuncSetAttribute(k_embed_ab,  cudaFuncAttributeMaxDynamicSharedMemorySize, EMBED_SMEM);
    cudaFuncSetAttribute(k_update_ab, cudaFuncAttributeMaxDynamicSharedMemorySize, UPDATE_SMEM);

    // CSR build (per call; deterministic up to fp-order in scatter)
    k_zero_deg<<<(N_NODES + 255) / 256, 256>>>();
    k_hist<<<(N_EDGES + 255) / 256, 256>>>(ei);
    k_scan<<<1, 1024>>>();
    k_scatter<<<(N_EDGES + 255) / 256, 256>>>(ei);

    k_embed_ab<<<N_NODES / 40, 640, EMBED_SMEM>>>(oh, pos, embW, embB, iW);
    for (int l = 0; l < 4; l++) {
        k_edge<<<N_NODES / 8, 512>>>(iB + l * 64);
        if (l < 3)
            k_update_ab<<<N_NODES / 40, 640, UPDATE_SMEM>>>(
                uW + (size_t)l * 4096, uB + l * 64, iW + (size_t)(l + 1) * 8192);
        else
            k_update_out<<<N_NODES / 40, 640>>>(
                uW + (size_t)l * 4096, uB + l * 64, oW, oB, out);
    }
}

// round 4
// speedup vs baseline: 1.6865x; 1.3475x over previous
#include <cuda_runtime.h>
#include <cstdint>

#define N_NODES 50000
#define N_EDGES 800000
#define H 64

// ---------------- scratch (device globals; no allocations) ----------------
__device__ __align__(16) float g_x0 [N_NODES * H];
__device__ __align__(16) float g_x  [N_NODES * H];
__device__ __align__(16) float g_a  [N_NODES * H];
__device__ __align__(16) float g_b  [N_NODES * H];
__device__ __align__(16) float g_acc[N_NODES * H];
__device__ int g_deg[N_NODES];
__device__ int g_off[N_NODES + 1];
__device__ int g_cursor[N_NODES];
__device__ int g_csr[N_EDGES];

// silu(z) = z * sigmoid(z) = 0.5*z*(1 + tanh(z/2)) -- single MUFU.TANH
__device__ __forceinline__ float silu_f(float z) {
    float t;
    asm("tanh.approx.f32 %0, %1;" : "=f"(t) : "f"(0.5f * z));
    return 0.5f * z * (1.0f + t);
}
__device__ __forceinline__ float4 silu4(float4 z) {
    return make_float4(silu_f(z.x), silu_f(z.y), silu_f(z.z), silu_f(z.w));
}
__device__ __forceinline__ float4 add4(float4 a, float4 b) {
    return make_float4(a.x + b.x, a.y + b.y, a.z + b.z, a.w + b.w);
}

// ============================ CSR construction =============================
__global__ void k_zero_deg() {
    int i = blockIdx.x * blockDim.x + threadIdx.x;
    if (i < N_NODES) g_deg[i] = 0;
}

__global__ void k_hist(const int* __restrict__ ei) {
    int e = blockIdx.x * blockDim.x + threadIdx.x;
    if (e < N_EDGES) atomicAdd(&g_deg[ei[e]], 1);
}

__global__ __launch_bounds__(1024) void k_scan() {
    __shared__ int warp_sums[32];
    __shared__ int s_carry;
    const int tid = threadIdx.x, lane = tid & 31, w = tid >> 5;
    if (tid == 0) { g_off[0] = 0; s_carry = 0; }
    __syncthreads();
    for (int base = 0; base < N_NODES; base += 1024) {
        int i = base + tid;
        int v = (i < N_NODES) ? g_deg[i] : 0;
        int x = v;
        #pragma unroll
        for (int o = 1; o < 32; o <<= 1) {
            int t = __shfl_up_sync(0xFFFFFFFFu, x, o);
            if (lane >= o) x += t;
        }
        if (lane == 31) warp_sums[w] = x;
        __syncthreads();
        if (w == 0) {
            int ws = warp_sums[lane];
            #pragma unroll
            for (int o = 1; o < 32; o <<= 1) {
                int t = __shfl_up_sync(0xFFFFFFFFu, ws, o);
                if (lane >= o) ws += t;
            }
            warp_sums[lane] = ws;
        }
        __syncthreads();
        int incl = x + (w ? warp_sums[w - 1] : 0) + s_carry;
        if (i < N_NODES) { g_off[i + 1] = incl; g_cursor[i] = incl - v; }
        __syncthreads();
        if (tid == 1023) s_carry = incl;
        __syncthreads();
    }
}

__global__ void k_scatter(const int* __restrict__ ei) {
    int e = blockIdx.x * blockDim.x + threadIdx.x;
    if (e < N_EDGES) {
        int s = ei[e];
        int p = atomicAdd(&g_cursor[s], 1);
        g_csr[p] = ei[N_EDGES + e];
    }
}

// ====================== fused embed + interact-GEMM(0) =====================
// 40 nodes/block, 640 threads; thread = 1 row x 4 cols.
__global__ __launch_bounds__(640) void k_embed_ab(
    const float* __restrict__ oh, const float* __restrict__ pos,
    const float* __restrict__ embW, const float* __restrict__ embB,
    const float* __restrict__ Wab0) {
    extern __shared__ float smem[];
    float* Ws   = smem;               // 7744
    float* Wab  = smem + 7744;        // 8192
    float* in_s = smem + 7744 + 8192; // 4840
    float* xs   = in_s + 4840;        // 2560
    const int tid = threadIdx.x;
    const int node0 = blockIdx.x * 40;
    {
        float4* d = (float4*)Ws; const float4* s = (const float4*)embW;
        for (int i = tid; i < 7744 / 4; i += 640) d[i] = s[i];
        float4* d2 = (float4*)Wab; const float4* s2 = (const float4*)Wab0;
        for (int i = tid; i < 8192 / 4; i += 640) d2[i] = s2[i];
    }
    for (int i = tid; i < 40 * 118; i += 640) {
        int row = i / 118, k = i % 118;
        in_s[row * 121 + k] = oh[(size_t)(node0 + row) * 118 + k];
    }
    for (int i = tid; i < 40 * 3; i += 640) {
        int row = i / 3, k = i % 3;
        in_s[row * 121 + 118 + k] = pos[(size_t)(node0 + row) * 3 + k];
    }
    __syncthreads();
    const int r = tid >> 4, cg = tid & 15;
    const int node = node0 + r;
    const float4* Ws4 = (const float4*)Ws;
    float4 acc = __ldg((const float4*)(embB) + cg);
    #pragma unroll 8
    for (int k = 0; k < 121; k++) {
        float h = in_s[r * 121 + k];
        float4 w = Ws4[k * 16 + cg];
        acc.x = fmaf(h, w.x, acc.x); acc.y = fmaf(h, w.y, acc.y);
        acc.z = fmaf(h, w.z, acc.z); acc.w = fmaf(h, w.w, acc.w);
    }
    float4 xv = silu4(acc);
    *(float4*)(g_x0 + (size_t)node * 64 + cg * 4) = xv;
    *(float4*)(g_x  + (size_t)node * 64 + cg * 4) = xv;
    ((float4*)xs)[r * 16 + cg] = xv;
    __syncthreads();
    const float4* Wa4 = (const float4*)Wab;
    const float4* Wb4 = Wa4 + 1024;
    float4 a4 = make_float4(0, 0, 0, 0), b4 = a4;
    #pragma unroll 8
    for (int k = 0; k < 64; k++) {
        float x = xs[r * 64 + k];
        float4 wa = Wa4[k * 16 + cg], wb = Wb4[k * 16 + cg];
        a4.x = fmaf(x, wa.x, a4.x); a4.y = fmaf(x, wa.y, a4.y);
        a4.z = fmaf(x, wa.z, a4.z); a4.w = fmaf(x, wa.w, a4.w);
        b4.x = fmaf(x, wb.x, b4.x); b4.y = fmaf(x, wb.y, b4.y);
        b4.z = fmaf(x, wb.z, b4.z); b4.w = fmaf(x, wb.w, b4.w);
    }
    *(float4*)(g_a + (size_t)node * 64 + cg * 4) = a4;
    *(float4*)(g_b + (size_t)node * 64 + cg * 4) = b4;
}

// ========================== CSR edge aggregation ===========================
// acc[s] = sum_{d in N(s)} silu(a[s] + b[d] + bias); 16 threads x float4 per node
__global__ __launch_bounds__(512) void k_edge(const float* __restrict__ bias) {
    const int tid = threadIdx.x;
    const int s = blockIdx.x * 32 + (tid >> 4);
    if (s >= N_NODES) return;
    const int c4 = tid & 15;
    float4 a4 = *(const float4*)(g_a + (size_t)s * 64 + c4 * 4);
    a4 = add4(a4, __ldg((const float4*)bias + c4));
    int j = g_off[s];
    const int end = g_off[s + 1];
    float4 acc = make_float4(0, 0, 0, 0);
    for (; j + 1 < end; j += 2) {
        int d0 = __ldg(g_csr + j);
        int d1 = __ldg(g_csr + j + 1);
        float4 b0 = *(const float4*)(g_b + (size_t)d0 * 64 + c4 * 4);
        float4 b1 = *(const float4*)(g_b + (size_t)d1 * 64 + c4 * 4);
        acc = add4(acc, silu4(add4(a4, b0)));
        acc = add4(acc, silu4(add4(a4, b1)));
    }
    if (j < end) {
        int d = __ldg(g_csr + j);
        float4 b0 = *(const float4*)(g_b + (size_t)d * 64 + c4 * 4);
        acc = add4(acc, silu4(add4(a4, b0)));
    }
    *(float4*)(g_acc + (size_t)s * 64 + c4 * 4) = acc;
}

// =================== fused update(l) + interact-GEMM(l+1) ==================
// 80 nodes/block, 640 threads; thread = 2 rows x 4 cols (halves weight LDS).
// dyn smem: U[4096] | Wab[8192] | xs[5120] | hs[5120]
__global__ __launch_bounds__(640) void k_update_ab(
    const float* __restrict__ U, const float* __restrict__ ub,
    const float* __restrict__ Wabn) {
    extern __shared__ float smem[];
    float* Us  = smem;
    float* Wab = smem + 4096;
    float* xs  = smem + 4096 + 8192;
    float* hs  = xs + 5120;
    const int tid = threadIdx.x;
    const int node0 = blockIdx.x * 80;
    {
        float4* d = (float4*)Us; const float4* s = (const float4*)U;
        for (int i = tid; i < 1024; i += 640) d[i] = s[i];
        float4* d2 = (float4*)Wab; const float4* s2 = (const float4*)Wabn;
        for (int i = tid; i < 2048; i += 640) d2[i] = s2[i];
    }
    for (int i = tid; i < 1280; i += 640) {
        int row = i >> 4, c4 = i & 15;
        float4 xv = *(const float4*)(g_x   + (size_t)(node0 + row) * 64 + c4 * 4);
        float4 av = *(const float4*)(g_acc + (size_t)(node0 + row) * 64 + c4 * 4);
        ((float4*)xs)[i] = xv;
        ((float4*)hs)[i] = make_float4(xv.x + 0.25f * av.x, xv.y + 0.25f * av.y,
                                       xv.z + 0.25f * av.z, xv.w + 0.25f * av.w);
    }
    __syncthreads();
    const int rl = tid >> 4, cg = tid & 15;   // rows rl and rl+40
    const float4* Us4 = (const float4*)Us;
    float4 bias4 = __ldg((const float4*)(ub) + cg);
    float4 acc0 = bias4, acc1 = bias4;
    #pragma unroll 8
    for (int k = 0; k < 64; k++) {
        float4 w = Us4[k * 16 + cg];
        float h0 = hs[rl * 64 + k];
        float h1 = hs[(rl + 40) * 64 + k];
        acc0.x = fmaf(h0, w.x, acc0.x); acc0.y = fmaf(h0, w.y, acc0.y);
        acc0.z = fmaf(h0, w.z, acc0.z); acc0.w = fmaf(h0, w.w, acc0.w);
        acc1.x = fmaf(h1, w.x, acc1.x); acc1.y = fmaf(h1, w.y, acc1.y);
        acc1.z = fmaf(h1, w.z, acc1.z); acc1.w = fmaf(h1, w.w, acc1.w);
    }
    float4 sv0 = silu4(acc0), sv1 = silu4(acc1);
    float4 xo0 = ((float4*)xs)[rl * 16 + cg];
    float4 xo1 = ((float4*)xs)[(rl + 40) * 16 + cg];
    float4 xn0 = add4(xo0, sv0), xn1 = add4(xo1, sv1);
    *(float4*)(g_x + (size_t)(node0 + rl) * 64 + cg * 4) = xn0;
    *(float4*)(g_x + (size_t)(node0 + rl + 40) * 64 + cg * 4) = xn1;
    ((float4*)xs)[rl * 16 + cg] = xn0;
    ((float4*)xs)[(rl + 40) * 16 + cg] = xn1;
    __syncthreads();
    const float4* Wa4 = (const float4*)Wab;
    const float4* Wb4 = Wa4 + 1024;
    float4 a0 = make_float4(0, 0, 0, 0), b0 = a0, a1 = a0, b1 = a0;
    #pragma unroll 4
    for (int k = 0; k < 64; k++) {
        float4 wa = Wa4[k * 16 + cg], wb = Wb4[k * 16 + cg];
        float x0 = xs[rl * 64 + k];
        float x1 = xs[(rl + 40) * 64 + k];
        a0.x = fmaf(x0, wa.x, a0.x); a0.y = fmaf(x0, wa.y, a0.y);
        a0.z = fmaf(x0, wa.z, a0.z); a0.w = fmaf(x0, wa.w, a0.w);
        b0.x = fmaf(x0, wb.x, b0.x); b0.y = fmaf(x0, wb.y, b0.y);
        b0.z = fmaf(x0, wb.z, b0.z); b0.w = fmaf(x0, wb.w, b0.w);
        a1.x = fmaf(x1, wa.x, a1.x); a1.y = fmaf(x1, wa.y, a1.y);
        a1.z = fmaf(x1, wa.z, a1.z); a1.w = fmaf(x1, wa.w, a1.w);
        b1.x = fmaf(x1, wb.x, b1.x); b1.y = fmaf(x1, wb.y, b1.y);
        b1.z = fmaf(x1, wb.z, b1.z); b1.w = fmaf(x1, wb.w, b1.w);
    }
    *(float4*)(g_a + (size_t)(node0 + rl) * 64 + cg * 4) = a0;
    *(float4*)(g_b + (size_t)(node0 + rl) * 64 + cg * 4) = b0;
    *(float4*)(g_a + (size_t)(node0 + rl + 40) * 64 + cg * 4) = a1;
    *(float4*)(g_b + (size_t)(node0 + rl + 40) * 64 + cg * 4) = b1;
}

// ====================== fused update(3) + output head ======================
__global__ __launch_bounds__(640) void k_update_out(
    const float* __restrict__ U, const float* __restrict__ ub,
    const float* __restrict__ Wo, const float* __restrict__ bo,
    float* __restrict__ out) {
    __shared__ float Us[4096];
    __shared__ float xs[2560];
    __shared__ float hs[2560];
    __shared__ float Wos[192];
    const int tid = threadIdx.x;
    const int node0 = blockIdx.x * 40;
    {
        float4* d = (float4*)Us; const float4* s = (const float4*)U;
        for (int i = tid; i < 1024; i += 640) d[i] = s[i];
        if (tid < 192) Wos[tid] = Wo[tid];
    }
    {
        int row = tid >> 4, c4 = tid & 15;
        float4 xv = *(const float4*)(g_x   + (size_t)(node0 + row) * 64 + c4 * 4);
        float4 av = *(const float4*)(g_acc + (size_t)(node0 + row) * 64 + c4 * 4);
        ((float4*)xs)[tid] = xv;
        ((float4*)hs)[tid] = make_float4(xv.x + 0.25f * av.x, xv.y + 0.25f * av.y,
                                         xv.z + 0.25f * av.z, xv.w + 0.25f * av.w);
    }
    __syncthreads();
    const int r = tid >> 4, cg = tid & 15;
    const int node = node0 + r;
    const float4* Us4 = (const float4*)Us;
    float4 acc = __ldg((const float4*)(ub) + cg);
    #pragma unroll 8
    for (int k = 0; k < 64; k++) {
        float h = hs[r * 64 + k];
        float4 w = Us4[k * 16 + cg];
        acc.x = fmaf(h, w.x, acc.x); acc.y = fmaf(h, w.y, acc.y);
        acc.z = fmaf(h, w.z, acc.z); acc.w = fmaf(h, w.w, acc.w);
    }
    float4 sv = silu4(acc);
    float4 xo = ((float4*)xs)[r * 16 + cg];
    float4 x0v = *(const float4*)(g_x0 + (size_t)node * 64 + cg * 4);
    float4 v = make_float4(x0v.x + xo.x + sv.x, x0v.y + xo.y + sv.y,
                           x0v.z + xo.z + sv.z, x0v.w + xo.w + sv.w);
    float p0, p1, p2;
    const int cb = cg * 4;
    p0 = v.x * Wos[(cb + 0) * 3 + 0] + v.y * Wos[(cb + 1) * 3 + 0]
       + v.z * Wos[(cb + 2) * 3 + 0] + v.w * Wos[(cb + 3) * 3 + 0];
    p1 = v.x * Wos[(cb + 0) * 3 + 1] + v.y * Wos[(cb + 1) * 3 + 1]
       + v.z * Wos[(cb + 2) * 3 + 1] + v.w * Wos[(cb + 3) * 3 + 1];
    p2 = v.x * Wos[(cb + 0) * 3 + 2] + v.y * Wos[(cb + 1) * 3 + 2]
       + v.z * Wos[(cb + 2) * 3 + 2] + v.w * Wos[(cb + 3) * 3 + 2];
    #pragma unroll
    for (int off = 8; off > 0; off >>= 1) {
        p0 += __shfl_down_sync(0xFFFFFFFFu, p0, off, 16);
        p1 += __shfl_down_sync(0xFFFFFFFFu, p1, off, 16);
        p2 += __shfl_down_sync(0xFFFFFFFFu, p2, off, 16);
    }
    if (cg == 0) {
        out[node * 3 + 0] = p0 + __ldg(bo + 0);
        out[node * 3 + 1] = p1 + __ldg(bo + 1);
        out[node * 3 + 2] = p2 + __ldg(bo + 2);
    }
}

// ================================ launcher =================================
extern "C" void kernel_launch(void* const* d_in, const int* in_sizes, int n_in,
                              void* d_out, int out_size) {
    const float* oh   = (const float*)d_in[0];
    const float* pos  = (const float*)d_in[1];
    const int*   ei   = (const int*)d_in[2];
    const float* embW = (const float*)d_in[3];
    const float* embB = (const float*)d_in[4];
    const float* iW   = (const float*)d_in[5];   // [4, 128, 64]
    const float* iB   = (const float*)d_in[6];   // [4, 64]
    const float* uW   = (const float*)d_in[7];   // [4, 64, 64]
    const float* uB   = (const float*)d_in[8];   // [4, 64]
    const float* oW   = (const float*)d_in[9];   // [64, 3]
    const float* oB   = (const float*)d_in[10];  // [3]
    float* out = (float*)d_out;

    const int EMBED_SMEM  = (7744 + 8192 + 4840 + 2560) * 4;  // 93,344 B
    const int UPDATE_SMEM = (4096 + 8192 + 5120 + 5120) * 4;  // 90,112 B
    cudaFuncSetAttribute(k_embed_ab,  cudaFuncAttributeMaxDynamicSharedMemorySize, EMBED_SMEM);
    cudaFuncSetAttribute(k_update_ab, cudaFuncAttributeMaxDynamicSharedMemorySize, UPDATE_SMEM);

    k_zero_deg<<<(N_NODES + 255) / 256, 256>>>();
    k_hist<<<(N_EDGES + 255) / 256, 256>>>(ei);
    k_scan<<<1, 1024>>>();
    k_scatter<<<(N_EDGES + 255) / 256, 256>>>(ei);

    k_embed_ab<<<N_NODES / 40, 640, EMBED_SMEM>>>(oh, pos, embW, embB, iW);
    for (int l = 0; l < 4; l++) {
        k_edge<<<(N_NODES + 31) / 32, 512>>>(iB + l * 64);
        if (l < 3)
            k_update_ab<<<N_NODES / 80, 640, UPDATE_SMEM>>>(
                uW + (size_t)l * 4096, uB + l * 64, iW + (size_t)(l + 1) * 8192);
        else
            k_update_out<<<N_NODES / 40, 640>>>(
                uW + (size_t)l * 4096, uB + l * 64, oW, oB, out);
    }
}